// round 14
// baseline (speedup 1.0000x reference)
#include <cuda_runtime.h>
#include <cstdint>

// ---------------- scratch (device globals; no allocation) ----------------
#define NMAX 50000
#define EMAX 800000
__device__ float g_h1 [NMAX * 128];   // (x@W1)*inv, later h2 (GAT transform, unscaled)
__device__ float g_agg[NMAX * 128];   // relu(GCN1) output
__device__ float g_inv[NMAX];         // rsqrt(deg)
__device__ float g_as [NMAX * 2];     // GAT a_src per (node, head)
__device__ float g_ad [NMAX * 2];     // GAT a_dst per (node, head)
__device__ float g_hx [NMAX * 64];    // elu(mean-head GAT) = GCN2 input
__device__ float g_h3 [NMAX * 64];    // (hx @ W3)*inv
__device__ int   g_deg[NMAX];
__device__ int   g_off[NMAX];
__device__ int   g_cur[NMAX];
__device__ int   g_srcs[EMAX];        // src ids bucketed by dst
__device__ unsigned g_total;
__device__ float g_maxas[2];          // global per-head max of a_src

__device__ __forceinline__ float leaky(float v) { return v > 0.f ? v : 0.2f * v; }

__device__ __forceinline__ void atomicMaxF(float* a, float v) {
    if (v >= 0.f) atomicMax((int*)a, __float_as_int(v));
    else          atomicMin((unsigned int*)a, __float_as_uint(v));
}

// ---------------- degree + CSR build ----------------
__global__ void k_zero_deg(int* deg, unsigned* total, float* maxas, int n) {
    int i = blockIdx.x * blockDim.x + threadIdx.x;
    if (i < n) deg[i] = 0;
    if (i == 0) { *total = 0u; maxas[0] = -3e38f; maxas[1] = -3e38f; }
}
__global__ void k_deg_count(const int* __restrict__ dst, int* deg, int E) {
    int base = (blockIdx.x * blockDim.x + threadIdx.x) * 4;
    #pragma unroll
    for (int j = 0; j < 4; j++) {
        int i = base + j;
        if (i < E) atomicAdd(&deg[dst[i]], 1);
    }
}
__global__ void k_offsets(const int* __restrict__ deg, int* off, int* cur,
                          float* inv, unsigned* total, int n) {
    int i = blockIdx.x * blockDim.x + threadIdx.x;
    int lane = threadIdx.x & 31;
    int d = (i < n) ? deg[i] : 0;
    int x = d;
    #pragma unroll
    for (int o = 1; o < 32; o <<= 1) {
        int y = __shfl_up_sync(0xffffffffu, x, o);
        if (lane >= o) x += y;
    }
    int wsum = __shfl_sync(0xffffffffu, x, 31);
    unsigned base = 0;
    if (lane == 31) base = atomicAdd(total, (unsigned)wsum);
    base = __shfl_sync(0xffffffffu, base, 31);
    int excl = (int)base + x - d;
    if (i < n) {
        off[i] = excl; cur[i] = excl;
        inv[i] = rsqrtf((float)(d + 1));
    }
}
__global__ void k_fill(const int* __restrict__ src, const int* __restrict__ dst,
                       int* cur, int* srcs, int E) {
    int base = (blockIdx.x * blockDim.x + threadIdx.x) * 4;
    #pragma unroll
    for (int j = 0; j < 4; j++) {
        int i = base + j;
        if (i < E) {
            int pos = atomicAdd(&cur[dst[i]], 1);
            srcs[pos] = src[i];
        }
    }
}

// ---------------- TF32 tensor-core GEMM with error compensation ----------------
// SCALE: multiply output rows by inv[row] (fused GCN degree pre-scaling)
__device__ __forceinline__ void split_tf32(float x, uint32_t& hi, uint32_t& lo) {
    uint32_t h;
    asm("cvt.rna.tf32.f32 %0, %1;" : "=r"(h) : "f"(x));
    float l = x - __uint_as_float(h);
    uint32_t lw;
    asm("cvt.rna.tf32.f32 %0, %1;" : "=r"(lw) : "f"(l));
    hi = h; lo = lw;
}
__device__ __forceinline__ void mma_tf32(float* c, const uint32_t* a, const uint32_t* b) {
    asm volatile("mma.sync.aligned.m16n8k8.row.col.f32.tf32.tf32.f32 "
        "{%0,%1,%2,%3},{%4,%5,%6,%7},{%8,%9},{%0,%1,%2,%3};"
        : "+f"(c[0]), "+f"(c[1]), "+f"(c[2]), "+f"(c[3])
        : "r"(a[0]), "r"(a[1]), "r"(a[2]), "r"(a[3]), "r"(b[0]), "r"(b[1]));
}

template<int K, int P, bool SCALE>
__global__ void __launch_bounds__(256)
gemm_tf32(const float* __restrict__ X, const float* __restrict__ W,
          float* __restrict__ Y, const float* __restrict__ inv, int n)
{
    constexpr int BM = 128;
    constexpr int BK = 32;
    constexpr int WARPS_N = P / 64;
    constexpr int WARPS_M = 8 / WARPS_N;
    constexpr int WM = BM / WARPS_M;
    constexpr int MF = WM / 16;
    constexpr int NF = 8;
    constexpr int XS = BK + 4;
    constexpr int WS = P + 8;

    __shared__ __align__(16) float Xs[BM * XS];
    __shared__ __align__(16) float Ws[BK * WS];

    int tid = threadIdx.x;
    int wid = tid >> 5, lane = tid & 31;
    int wm = wid % WARPS_M, wn = wid / WARPS_M;
    int g = lane >> 2, tg = lane & 3;

    int r0 = blockIdx.x * BM;
    int rows = n - r0; if (rows > BM) rows = BM;

    float c[MF][NF][4];
    #pragma unroll
    for (int mf = 0; mf < MF; mf++)
        #pragma unroll
        for (int nf = 0; nf < NF; nf++)
            #pragma unroll
            for (int q = 0; q < 4; q++) c[mf][nf][q] = 0.f;

    for (int kt = 0; kt < K; kt += BK) {
        #pragma unroll
        for (int i = tid; i < BK * P / 4; i += 256) {
            int k = i / (P / 4), c4 = (i % (P / 4)) * 4;
            *(float4*)&Ws[k * WS + c4] = *(const float4*)&W[(kt + k) * P + c4];
        }
        #pragma unroll
        for (int i = tid; i < BM * BK / 4; i += 256) {
            int r = i / (BK / 4), k4 = (i % (BK / 4)) * 4;
            float4 v = (r < rows) ? *(const float4*)&X[(size_t)(r0 + r) * K + kt + k4]
                                  : make_float4(0.f, 0.f, 0.f, 0.f);
            *(float4*)&Xs[r * XS + k4] = v;
        }
        __syncthreads();
        #pragma unroll
        for (int k8 = 0; k8 < BK; k8 += 8) {
            uint32_t ah[MF][4], al[MF][4];
            #pragma unroll
            for (int mf = 0; mf < MF; mf++) {
                int rb = wm * WM + mf * 16;
                split_tf32(Xs[(rb + g    ) * XS + k8 + tg    ], ah[mf][0], al[mf][0]);
                split_tf32(Xs[(rb + g + 8) * XS + k8 + tg    ], ah[mf][1], al[mf][1]);
                split_tf32(Xs[(rb + g    ) * XS + k8 + tg + 4], ah[mf][2], al[mf][2]);
                split_tf32(Xs[(rb + g + 8) * XS + k8 + tg + 4], ah[mf][3], al[mf][3]);
            }
            uint32_t bh[NF][2], bl[NF][2];
            #pragma unroll
            for (int nf = 0; nf < NF; nf++) {
                int col = wn * 64 + nf * 8 + g;
                split_tf32(Ws[(k8 + tg    ) * WS + col], bh[nf][0], bl[nf][0]);
                split_tf32(Ws[(k8 + tg + 4) * WS + col], bh[nf][1], bl[nf][1]);
            }
            #pragma unroll
            for (int mf = 0; mf < MF; mf++)
                #pragma unroll
                for (int nf = 0; nf < NF; nf++) {
                    mma_tf32(c[mf][nf], ah[mf], bh[nf]);
                    mma_tf32(c[mf][nf], ah[mf], bl[nf]);
                    mma_tf32(c[mf][nf], al[mf], bh[nf]);
                }
        }
        __syncthreads();
    }
    #pragma unroll
    for (int mf = 0; mf < MF; mf++) {
        int rb = wm * WM + mf * 16;
        int ra = rb + g, rc = rb + g + 8;
        float iva = 1.f, ivc = 1.f;
        if (SCALE) {
            if (ra < rows) iva = inv[r0 + ra];
            if (rc < rows) ivc = inv[r0 + rc];
        }
        #pragma unroll
        for (int nf = 0; nf < NF; nf++) {
            int col = wn * 64 + nf * 8 + 2 * tg;
            if (ra < rows)
                *(float2*)&Y[(size_t)(r0 + ra) * P + col] =
                    make_float2(c[mf][nf][0] * iva, c[mf][nf][1] * iva);
            if (rc < rows)
                *(float2*)&Y[(size_t)(r0 + rc) * P + col] =
                    make_float2(c[mf][nf][2] * ivc, c[mf][nf][3] * ivc);
        }
    }
}

// ---------------- GCN1 pull-aggregation (F=128) + relu: pure gather-add ----------------
// h is pre-scaled by inv[row]; out[d] = relu(invd * (h[d] + sum_s h[s]) + b)
__global__ void k_gcn1_agg(const float* __restrict__ h, const int* __restrict__ off,
                           const int* __restrict__ deg, const int* __restrict__ srcs,
                           const float* __restrict__ inv, const float* __restrict__ bias,
                           float* __restrict__ out, int n)
{
    int gid = blockIdx.x * blockDim.x + threadIdx.x;
    int d = gid >> 5, lane = gid & 31;
    if (d >= n) return;
    int beg = off[d], end = beg + deg[d];
    float invd = inv[d];

    float4 acc = *(const float4*)(h + (size_t)d * 128 + lane * 4);

    int i = beg;
    for (; i + 4 <= end; i += 4) {
        int s0 = srcs[i], s1 = srcs[i+1], s2 = srcs[i+2], s3 = srcs[i+3];
        float4 v0 = *(const float4*)(h + (size_t)s0 * 128 + lane * 4);
        float4 v1 = *(const float4*)(h + (size_t)s1 * 128 + lane * 4);
        float4 v2 = *(const float4*)(h + (size_t)s2 * 128 + lane * 4);
        float4 v3 = *(const float4*)(h + (size_t)s3 * 128 + lane * 4);
        acc.x += (v0.x + v1.x) + (v2.x + v3.x);
        acc.y += (v0.y + v1.y) + (v2.y + v3.y);
        acc.z += (v0.z + v1.z) + (v2.z + v3.z);
        acc.w += (v0.w + v1.w) + (v2.w + v3.w);
    }
    for (; i < end; i++) {
        int s = srcs[i];
        float4 v = *(const float4*)(h + (size_t)s * 128 + lane * 4);
        acc.x += v.x; acc.y += v.y; acc.z += v.z; acc.w += v.w;
    }
    float4 b = *(const float4*)&bias[lane * 4];
    acc.x = fmaxf(acc.x * invd + b.x, 0.f); acc.y = fmaxf(acc.y * invd + b.y, 0.f);
    acc.z = fmaxf(acc.z * invd + b.z, 0.f); acc.w = fmaxf(acc.w * invd + b.w, 0.f);
    *(float4*)(out + (size_t)d * 128 + lane * 4) = acc;
}

// ---------------- GAT scores: 1024-thread blocks, smem max, 2 atomics/block --------------
__global__ void __launch_bounds__(1024)
k_gat_scores(const float* __restrict__ h2, const float* __restrict__ att_s,
             const float* __restrict__ att_d, float* __restrict__ as_,
             float* __restrict__ ad_, float* __restrict__ maxas, int n)
{
    __shared__ float smax[2];
    if (threadIdx.x < 2) smax[threadIdx.x] = -3e38f;
    __syncthreads();

    int gid = blockIdx.x * blockDim.x + threadIdx.x;
    int w = gid >> 5, lane = gid & 31;
    if (w < n * 2) {
        int nn = w >> 1, hh = w & 1;
        const float* row = h2 + (size_t)nn * 128 + hh * 64;
        float v0 = row[lane], v1 = row[lane + 32];
        float s = v0 * att_s[hh * 64 + lane] + v1 * att_s[hh * 64 + lane + 32];
        float d = v0 * att_d[hh * 64 + lane] + v1 * att_d[hh * 64 + lane + 32];
        #pragma unroll
        for (int o = 16; o; o >>= 1) {
            s += __shfl_down_sync(0xffffffffu, s, o);
            d += __shfl_down_sync(0xffffffffu, d, o);
        }
        if (lane == 0) {
            as_[w] = s; ad_[w] = d;
            if (s >= 0.f) atomicMax((int*)&smax[hh], __float_as_int(s));
            else          atomicMin((unsigned int*)&smax[hh], __float_as_uint(s));
        }
    }
    __syncthreads();
    if (threadIdx.x < 2) atomicMaxF(&maxas[threadIdx.x], smax[threadIdx.x]);
}

// ---------------- GAT single-pass softmax+aggregation, 1 exp/edge/lane -------------------
__global__ void k_gat_agg(const float* __restrict__ h2, const int* __restrict__ off,
                          const int* __restrict__ deg, const int* __restrict__ srcs,
                          const float* __restrict__ as_, const float* __restrict__ ad_,
                          const float* __restrict__ maxas, const float* __restrict__ bg,
                          float* __restrict__ hx, int n)
{
    int gid = blockIdx.x * blockDim.x + threadIdx.x;
    int d = gid >> 5, lane = gid & 31;
    if (d >= n) return;
    int beg = off[d], end = beg + deg[d];
    bool h0 = lane < 16;
    int hh = h0 ? 0 : 1;

    float adS = ad_[d * 2 + hh];
    float cS  = leaky(maxas[hh] + adS);
    float exs = __expf(leaky(as_[d * 2 + hh] + adS) - cS);
    float den = exs;

    float4 sv = *(const float4*)(h2 + (size_t)d * 128 + lane * 4);
    float4 acc = make_float4(sv.x * exs, sv.y * exs, sv.z * exs, sv.w * exs);

    int i = beg;
    for (; i + 4 <= end; i += 4) {
        int s0 = srcs[i], s1 = srcs[i+1], s2 = srcs[i+2], s3 = srcs[i+3];
        float e0 = __expf(leaky(as_[s0 * 2 + hh] + adS) - cS);
        float e1 = __expf(leaky(as_[s1 * 2 + hh] + adS) - cS);
        float e2 = __expf(leaky(as_[s2 * 2 + hh] + adS) - cS);
        float e3 = __expf(leaky(as_[s3 * 2 + hh] + adS) - cS);
        den += (e0 + e1) + (e2 + e3);
        float4 v0 = *(const float4*)(h2 + (size_t)s0 * 128 + lane * 4);
        float4 v1 = *(const float4*)(h2 + (size_t)s1 * 128 + lane * 4);
        float4 v2 = *(const float4*)(h2 + (size_t)s2 * 128 + lane * 4);
        float4 v3 = *(const float4*)(h2 + (size_t)s3 * 128 + lane * 4);
        acc.x += v0.x*e0 + v1.x*e1 + v2.x*e2 + v3.x*e3;
        acc.y += v0.y*e0 + v1.y*e1 + v2.y*e2 + v3.y*e3;
        acc.z += v0.z*e0 + v1.z*e1 + v2.z*e2 + v3.z*e3;
        acc.w += v0.w*e0 + v1.w*e1 + v2.w*e2 + v3.w*e3;
    }
    for (; i < end; i++) {
        int s = srcs[i];
        float e = __expf(leaky(as_[s * 2 + hh] + adS) - cS);
        den += e;
        float4 v = *(const float4*)(h2 + (size_t)s * 128 + lane * 4);
        acc.x += v.x * e; acc.y += v.y * e; acc.z += v.z * e; acc.w += v.w * e;
    }
    float scale = __fdividef(1.f, den);
    acc.x *= scale; acc.y *= scale; acc.z *= scale; acc.w *= scale;

    float ox = __shfl_down_sync(0xffffffffu, acc.x, 16);
    float oy = __shfl_down_sync(0xffffffffu, acc.y, 16);
    float oz = __shfl_down_sync(0xffffffffu, acc.z, 16);
    float ow = __shfl_down_sync(0xffffffffu, acc.w, 16);
    if (h0) {
        float4 b = *(const float4*)&bg[lane * 4];
        float4 r;
        r.x = 0.5f * (acc.x + ox) + b.x;
        r.y = 0.5f * (acc.y + oy) + b.y;
        r.z = 0.5f * (acc.z + oz) + b.z;
        r.w = 0.5f * (acc.w + ow) + b.w;
        r.x = r.x > 0.f ? r.x : expm1f(r.x);
        r.y = r.y > 0.f ? r.y : expm1f(r.y);
        r.z = r.z > 0.f ? r.z : expm1f(r.z);
        r.w = r.w > 0.f ? r.w : expm1f(r.w);
        *(float4*)(hx + (size_t)d * 64 + lane * 4) = r;
    }
}

// ---------------- GCN2 pull-aggregation (F=64): pure gather-add ----------------
__global__ void k_gcn2_agg(const float* __restrict__ h, const int* __restrict__ off,
                           const int* __restrict__ deg, const int* __restrict__ srcs,
                           const float* __restrict__ inv, const float* __restrict__ bias,
                           float* __restrict__ out, int n)
{
    int gid = blockIdx.x * blockDim.x + threadIdx.x;
    int d = gid >> 5, lane = gid & 31;
    if (d >= n) return;
    int beg = off[d], end = beg + deg[d];
    float invd = inv[d];

    float2 acc = *(const float2*)(h + (size_t)d * 64 + lane * 2);

    int i = beg;
    for (; i + 4 <= end; i += 4) {
        int s0 = srcs[i], s1 = srcs[i+1], s2 = srcs[i+2], s3 = srcs[i+3];
        float2 v0 = *(const float2*)(h + (size_t)s0 * 64 + lane * 2);
        float2 v1 = *(const float2*)(h + (size_t)s1 * 64 + lane * 2);
        float2 v2 = *(const float2*)(h + (size_t)s2 * 64 + lane * 2);
        float2 v3 = *(const float2*)(h + (size_t)s3 * 64 + lane * 2);
        acc.x += (v0.x + v1.x) + (v2.x + v3.x);
        acc.y += (v0.y + v1.y) + (v2.y + v3.y);
    }
    for (; i < end; i++) {
        int s = srcs[i];
        float2 v = *(const float2*)(h + (size_t)s * 64 + lane * 2);
        acc.x += v.x; acc.y += v.y;
    }
    float2 b = *(const float2*)&bias[lane * 2];
    *(float2*)(out + (size_t)d * 64 + lane * 2) =
        make_float2(acc.x * invd + b.x, acc.y * invd + b.y);
}

// ---------------- host ----------------
static inline int up(int a, int b) { return (a + b - 1) / b; }

extern "C" void kernel_launch(void* const* d_in, const int* in_sizes, int n_in,
                              void* d_out, int out_size)
{
    const float* x       = (const float*)d_in[0];
    const int*   ei      = (const int*)d_in[1];    // int32 (JAX x64 disabled)
    const float* W1      = (const float*)d_in[2];
    const float* b1      = (const float*)d_in[3];
    const float* Wg      = (const float*)d_in[4];
    const float* att_src = (const float*)d_in[5];
    const float* att_dst = (const float*)d_in[6];
    const float* bg      = (const float*)d_in[7];
    const float* W3      = (const float*)d_in[8];
    const float* b3      = (const float*)d_in[9];
    float* out = (float*)d_out;

    int n = in_sizes[0] / 128;
    int E = in_sizes[1] / 2;
    const int* src = ei;
    const int* dst = ei + E;

    void* p;
    cudaGetSymbolAddress(&p, g_h1);    float* h1    = (float*)p;
    cudaGetSymbolAddress(&p, g_agg);   float* agg   = (float*)p;
    cudaGetSymbolAddress(&p, g_inv);   float* inv   = (float*)p;
    cudaGetSymbolAddress(&p, g_as);    float* as_   = (float*)p;
    cudaGetSymbolAddress(&p, g_ad);    float* ad_   = (float*)p;
    cudaGetSymbolAddress(&p, g_hx);    float* hx    = (float*)p;
    cudaGetSymbolAddress(&p, g_h3);    float* h3    = (float*)p;
    cudaGetSymbolAddress(&p, g_deg);   int*   deg   = (int*)p;
    cudaGetSymbolAddress(&p, g_off);   int*   off   = (int*)p;
    cudaGetSymbolAddress(&p, g_cur);   int*   cur   = (int*)p;
    cudaGetSymbolAddress(&p, g_srcs);  int*   srcs  = (int*)p;
    cudaGetSymbolAddress(&p, g_total); unsigned* total = (unsigned*)p;
    cudaGetSymbolAddress(&p, g_maxas); float* maxas = (float*)p;

    // fork-join side stream for CSR build (created once; capture-safe pattern)
    static cudaStream_t s2 = nullptr;
    static cudaEvent_t evFork = nullptr, evInv = nullptr, evJoin = nullptr;
    if (!s2) {
        cudaStreamCreateWithFlags(&s2, cudaStreamNonBlocking);
        cudaEventCreateWithFlags(&evFork, cudaEventDisableTiming);
        cudaEventCreateWithFlags(&evInv, cudaEventDisableTiming);
        cudaEventCreateWithFlags(&evJoin, cudaEventDisableTiming);
    }

    const int T = 256;

    // ---- fork: CSR build on s2; GEMM1 (needs inv) waits on evInv ----
    cudaEventRecord(evFork, 0);
    cudaStreamWaitEvent(s2, evFork, 0);

    k_zero_deg <<<up(n, T), T, 0, s2>>>(deg, total, maxas, n);
    k_deg_count<<<up(E, T * 4), T, 0, s2>>>(dst, deg, E);
    k_offsets  <<<up(n, T), T, 0, s2>>>(deg, off, cur, inv, total, n);
    cudaEventRecord(evInv, s2);
    k_fill     <<<up(E, T * 4), T, 0, s2>>>(src, dst, cur, srcs, E);
    cudaEventRecord(evJoin, s2);

    cudaStreamWaitEvent(0, evInv, 0);
    gemm_tf32<128,128,true><<<up(n, 128), 256>>>(x, W1, h1, inv, n);  // h1 = (x@W1)*inv

    cudaStreamWaitEvent(0, evJoin, 0);   // CSR fill done before first aggregation

    // ---- GCN layer 1 ----
    k_gcn1_agg<<<up(n * 32, T), T>>>(h1, off, deg, srcs, inv, b1, agg, n);

    // ---- GAT layer ----
    gemm_tf32<128,128,false><<<up(n, 128), 256>>>(agg, Wg, h1, inv, n);   // h2 in h1
    k_gat_scores<<<up(n * 64, 1024), 1024>>>(h1, att_src, att_dst, as_, ad_, maxas, n);
    k_gat_agg   <<<up(n * 32, T), T>>>(h1, off, deg, srcs, as_, ad_, maxas, bg, hx, n);

    // ---- GCN layer 2 ----
    gemm_tf32<64,64,true><<<up(n, 128), 256>>>(hx, W3, h3, inv, n);   // h3 = (hx@W3)*inv
    k_gcn2_agg<<<up(n * 32, T), T>>>(h3, off, deg, srcs, inv, b3, out, n);
}

// round 15
// speedup vs baseline: 1.0330x; 1.0330x over previous
#include <cuda_runtime.h>
#include <cstdint>

// ---------------- scratch (device globals; no allocation) ----------------
#define NMAX 50000
#define EMAX 800000
__device__ float g_h1 [NMAX * 128];   // x@W1, later h2 (GAT transform)
__device__ float g_agg[NMAX * 128];   // relu(GCN1) output
__device__ float g_inv[NMAX];         // rsqrt(deg)
__device__ float g_as [NMAX * 2];     // GAT a_src per (node, head)
__device__ float g_ad [NMAX * 2];     // GAT a_dst per (node, head)
__device__ float g_hx [NMAX * 64];    // elu(mean-head GAT) = GCN2 input
__device__ float g_h3 [NMAX * 64];    // (hx @ W3)*inv
__device__ int   g_deg[NMAX];
__device__ int   g_off[NMAX];
__device__ int   g_cur[NMAX];
__device__ int   g_srcs[EMAX];        // src ids bucketed by dst
__device__ unsigned g_total;
__device__ float g_maxas[2];          // global per-head max of a_src

__device__ __forceinline__ float leaky(float v) { return v > 0.f ? v : 0.2f * v; }

__device__ __forceinline__ void atomicMaxF(float* a, float v) {
    if (v >= 0.f) atomicMax((int*)a, __float_as_int(v));
    else          atomicMin((unsigned int*)a, __float_as_uint(v));
}

// ---------------- degree + CSR build ----------------
__global__ void k_zero_deg(int* deg, unsigned* total, float* maxas, int n) {
    int i = blockIdx.x * blockDim.x + threadIdx.x;
    if (i < n) deg[i] = 0;
    if (i == 0) { *total = 0u; maxas[0] = -3e38f; maxas[1] = -3e38f; }
}
__global__ void k_deg_count(const int* __restrict__ dst, int* deg, int E) {
    int base = (blockIdx.x * blockDim.x + threadIdx.x) * 4;
    #pragma unroll
    for (int j = 0; j < 4; j++) {
        int i = base + j;
        if (i < E) atomicAdd(&deg[dst[i]], 1);
    }
}
__global__ void k_offsets(const int* __restrict__ deg, int* off, int* cur,
                          float* inv, unsigned* total, int n) {
    int i = blockIdx.x * blockDim.x + threadIdx.x;
    int lane = threadIdx.x & 31;
    int d = (i < n) ? deg[i] : 0;
    int x = d;
    #pragma unroll
    for (int o = 1; o < 32; o <<= 1) {
        int y = __shfl_up_sync(0xffffffffu, x, o);
        if (lane >= o) x += y;
    }
    int wsum = __shfl_sync(0xffffffffu, x, 31);
    unsigned base = 0;
    if (lane == 31) base = atomicAdd(total, (unsigned)wsum);
    base = __shfl_sync(0xffffffffu, base, 31);
    int excl = (int)base + x - d;
    if (i < n) {
        off[i] = excl; cur[i] = excl;
        inv[i] = rsqrtf((float)(d + 1));
    }
}
__global__ void k_fill(const int* __restrict__ src, const int* __restrict__ dst,
                       int* cur, int* srcs, int E) {
    int base = (blockIdx.x * blockDim.x + threadIdx.x) * 4;
    #pragma unroll
    for (int j = 0; j < 4; j++) {
        int i = base + j;
        if (i < E) {
            int pos = atomicAdd(&cur[dst[i]], 1);
            srcs[pos] = src[i];
        }
    }
}

// ---------------- TF32 tensor-core GEMM with error compensation ----------------
// SCALE: multiply output rows by inv[row] (fused GCN degree pre-scaling)
__device__ __forceinline__ void split_tf32(float x, uint32_t& hi, uint32_t& lo) {
    uint32_t h;
    asm("cvt.rna.tf32.f32 %0, %1;" : "=r"(h) : "f"(x));
    float l = x - __uint_as_float(h);
    uint32_t lw;
    asm("cvt.rna.tf32.f32 %0, %1;" : "=r"(lw) : "f"(l));
    hi = h; lo = lw;
}
__device__ __forceinline__ void mma_tf32(float* c, const uint32_t* a, const uint32_t* b) {
    asm volatile("mma.sync.aligned.m16n8k8.row.col.f32.tf32.tf32.f32 "
        "{%0,%1,%2,%3},{%4,%5,%6,%7},{%8,%9},{%0,%1,%2,%3};"
        : "+f"(c[0]), "+f"(c[1]), "+f"(c[2]), "+f"(c[3])
        : "r"(a[0]), "r"(a[1]), "r"(a[2]), "r"(a[3]), "r"(b[0]), "r"(b[1]));
}

template<int K, int P, bool SCALE>
__global__ void __launch_bounds__(256)
gemm_tf32(const float* __restrict__ X, const float* __restrict__ W,
          float* __restrict__ Y, const float* __restrict__ inv, int n)
{
    constexpr int BM = 128;
    constexpr int BK = 32;
    constexpr int WARPS_N = P / 64;
    constexpr int WARPS_M = 8 / WARPS_N;
    constexpr int WM = BM / WARPS_M;
    constexpr int MF = WM / 16;
    constexpr int NF = 8;
    constexpr int XS = BK + 4;
    constexpr int WS = P + 8;

    __shared__ __align__(16) float Xs[BM * XS];
    __shared__ __align__(16) float Ws[BK * WS];

    int tid = threadIdx.x;
    int wid = tid >> 5, lane = tid & 31;
    int wm = wid % WARPS_M, wn = wid / WARPS_M;
    int g = lane >> 2, tg = lane & 3;

    int r0 = blockIdx.x * BM;
    int rows = n - r0; if (rows > BM) rows = BM;

    float c[MF][NF][4];
    #pragma unroll
    for (int mf = 0; mf < MF; mf++)
        #pragma unroll
        for (int nf = 0; nf < NF; nf++)
            #pragma unroll
            for (int q = 0; q < 4; q++) c[mf][nf][q] = 0.f;

    for (int kt = 0; kt < K; kt += BK) {
        #pragma unroll
        for (int i = tid; i < BK * P / 4; i += 256) {
            int k = i / (P / 4), c4 = (i % (P / 4)) * 4;
            *(float4*)&Ws[k * WS + c4] = *(const float4*)&W[(kt + k) * P + c4];
        }
        #pragma unroll
        for (int i = tid; i < BM * BK / 4; i += 256) {
            int r = i / (BK / 4), k4 = (i % (BK / 4)) * 4;
            float4 v = (r < rows) ? *(const float4*)&X[(size_t)(r0 + r) * K + kt + k4]
                                  : make_float4(0.f, 0.f, 0.f, 0.f);
            *(float4*)&Xs[r * XS + k4] = v;
        }
        __syncthreads();
        #pragma unroll
        for (int k8 = 0; k8 < BK; k8 += 8) {
            uint32_t ah[MF][4], al[MF][4];
            #pragma unroll
            for (int mf = 0; mf < MF; mf++) {
                int rb = wm * WM + mf * 16;
                split_tf32(Xs[(rb + g    ) * XS + k8 + tg    ], ah[mf][0], al[mf][0]);
                split_tf32(Xs[(rb + g + 8) * XS + k8 + tg    ], ah[mf][1], al[mf][1]);
                split_tf32(Xs[(rb + g    ) * XS + k8 + tg + 4], ah[mf][2], al[mf][2]);
                split_tf32(Xs[(rb + g + 8) * XS + k8 + tg + 4], ah[mf][3], al[mf][3]);
            }
            uint32_t bh[NF][2], bl[NF][2];
            #pragma unroll
            for (int nf = 0; nf < NF; nf++) {
                int col = wn * 64 + nf * 8 + g;
                split_tf32(Ws[(k8 + tg    ) * WS + col], bh[nf][0], bl[nf][0]);
                split_tf32(Ws[(k8 + tg + 4) * WS + col], bh[nf][1], bl[nf][1]);
            }
            #pragma unroll
            for (int mf = 0; mf < MF; mf++)
                #pragma unroll
                for (int nf = 0; nf < NF; nf++) {
                    mma_tf32(c[mf][nf], ah[mf], bh[nf]);
                    mma_tf32(c[mf][nf], ah[mf], bl[nf]);
                    mma_tf32(c[mf][nf], al[mf], bh[nf]);
                }
        }
        __syncthreads();
    }
    #pragma unroll
    for (int mf = 0; mf < MF; mf++) {
        int rb = wm * WM + mf * 16;
        int ra = rb + g, rc = rb + g + 8;
        float iva = 1.f, ivc = 1.f;
        if (SCALE) {
            if (ra < rows) iva = inv[r0 + ra];
            if (rc < rows) ivc = inv[r0 + rc];
        }
        #pragma unroll
        for (int nf = 0; nf < NF; nf++) {
            int col = wn * 64 + nf * 8 + 2 * tg;
            if (ra < rows)
                *(float2*)&Y[(size_t)(r0 + ra) * P + col] =
                    make_float2(c[mf][nf][0] * iva, c[mf][nf][1] * iva);
            if (rc < rows)
                *(float2*)&Y[(size_t)(r0 + rc) * P + col] =
                    make_float2(c[mf][nf][2] * ivc, c[mf][nf][3] * ivc);
        }
    }
}

// ---------------- GCN1 pull-aggregation (F=128) + relu, warp/node, unroll-4 ----------------
__global__ void k_gcn1_agg(const float* __restrict__ h, const int* __restrict__ off,
                           const int* __restrict__ deg, const int* __restrict__ srcs,
                           const float* __restrict__ inv, const float* __restrict__ bias,
                           float* __restrict__ out, int n)
{
    int gid = blockIdx.x * blockDim.x + threadIdx.x;
    int d = gid >> 5, lane = gid & 31;
    if (d >= n) return;
    int beg = off[d], end = beg + deg[d];
    float invd = inv[d];

    float4 sv = *(const float4*)(h + (size_t)d * 128 + lane * 4);
    float cs = invd * invd;
    float4 acc = make_float4(sv.x * cs, sv.y * cs, sv.z * cs, sv.w * cs);

    int i = beg;
    for (; i + 4 <= end; i += 4) {
        int s0 = srcs[i], s1 = srcs[i+1], s2 = srcs[i+2], s3 = srcs[i+3];
        float c0 = inv[s0] * invd, c1 = inv[s1] * invd;
        float c2 = inv[s2] * invd, c3 = inv[s3] * invd;
        float4 v0 = *(const float4*)(h + (size_t)s0 * 128 + lane * 4);
        float4 v1 = *(const float4*)(h + (size_t)s1 * 128 + lane * 4);
        float4 v2 = *(const float4*)(h + (size_t)s2 * 128 + lane * 4);
        float4 v3 = *(const float4*)(h + (size_t)s3 * 128 + lane * 4);
        acc.x += v0.x*c0 + v1.x*c1 + v2.x*c2 + v3.x*c3;
        acc.y += v0.y*c0 + v1.y*c1 + v2.y*c2 + v3.y*c3;
        acc.z += v0.z*c0 + v1.z*c1 + v2.z*c2 + v3.z*c3;
        acc.w += v0.w*c0 + v1.w*c1 + v2.w*c2 + v3.w*c3;
    }
    for (; i < end; i++) {
        int s = srcs[i];
        float c = inv[s] * invd;
        float4 v = *(const float4*)(h + (size_t)s * 128 + lane * 4);
        acc.x += v.x * c; acc.y += v.y * c; acc.z += v.z * c; acc.w += v.w * c;
    }
    float4 b = *(const float4*)&bias[lane * 4];
    acc.x = fmaxf(acc.x + b.x, 0.f); acc.y = fmaxf(acc.y + b.y, 0.f);
    acc.z = fmaxf(acc.z + b.z, 0.f); acc.w = fmaxf(acc.w + b.w, 0.f);
    *(float4*)(out + (size_t)d * 128 + lane * 4) = acc;
}

// ---------------- GAT scores: 1024-thread blocks, smem max, 2 atomics/block --------------
__global__ void __launch_bounds__(1024)
k_gat_scores(const float* __restrict__ h2, const float* __restrict__ att_s,
             const float* __restrict__ att_d, float* __restrict__ as_,
             float* __restrict__ ad_, float* __restrict__ maxas, int n)
{
    __shared__ float smax[2];
    if (threadIdx.x < 2) smax[threadIdx.x] = -3e38f;
    __syncthreads();

    int gid = blockIdx.x * blockDim.x + threadIdx.x;
    int w = gid >> 5, lane = gid & 31;
    if (w < n * 2) {
        int nn = w >> 1, hh = w & 1;
        const float* row = h2 + (size_t)nn * 128 + hh * 64;
        float v0 = row[lane], v1 = row[lane + 32];
        float s = v0 * att_s[hh * 64 + lane] + v1 * att_s[hh * 64 + lane + 32];
        float d = v0 * att_d[hh * 64 + lane] + v1 * att_d[hh * 64 + lane + 32];
        #pragma unroll
        for (int o = 16; o; o >>= 1) {
            s += __shfl_down_sync(0xffffffffu, s, o);
            d += __shfl_down_sync(0xffffffffu, d, o);
        }
        if (lane == 0) {
            as_[w] = s; ad_[w] = d;
            if (s >= 0.f) atomicMax((int*)&smax[hh], __float_as_int(s));
            else          atomicMin((unsigned int*)&smax[hh], __float_as_uint(s));
        }
    }
    __syncthreads();
    if (threadIdx.x < 2) atomicMaxF(&maxas[threadIdx.x], smax[threadIdx.x]);
}

// ---------------- GAT single-pass softmax+aggregation, 1 exp/edge/lane -------------------
__global__ void k_gat_agg(const float* __restrict__ h2, const int* __restrict__ off,
                          const int* __restrict__ deg, const int* __restrict__ srcs,
                          const float* __restrict__ as_, const float* __restrict__ ad_,
                          const float* __restrict__ maxas, const float* __restrict__ bg,
                          float* __restrict__ hx, int n)
{
    int gid = blockIdx.x * blockDim.x + threadIdx.x;
    int d = gid >> 5, lane = gid & 31;
    if (d >= n) return;
    int beg = off[d], end = beg + deg[d];
    bool h0 = lane < 16;
    int hh = h0 ? 0 : 1;

    float adS = ad_[d * 2 + hh];
    float cS  = leaky(maxas[hh] + adS);
    float exs = __expf(leaky(as_[d * 2 + hh] + adS) - cS);
    float den = exs;

    float4 sv = *(const float4*)(h2 + (size_t)d * 128 + lane * 4);
    float4 acc = make_float4(sv.x * exs, sv.y * exs, sv.z * exs, sv.w * exs);

    int i = beg;
    for (; i + 4 <= end; i += 4) {
        int s0 = srcs[i], s1 = srcs[i+1], s2 = srcs[i+2], s3 = srcs[i+3];
        float e0 = __expf(leaky(as_[s0 * 2 + hh] + adS) - cS);
        float e1 = __expf(leaky(as_[s1 * 2 + hh] + adS) - cS);
        float e2 = __expf(leaky(as_[s2 * 2 + hh] + adS) - cS);
        float e3 = __expf(leaky(as_[s3 * 2 + hh] + adS) - cS);
        den += (e0 + e1) + (e2 + e3);
        float4 v0 = *(const float4*)(h2 + (size_t)s0 * 128 + lane * 4);
        float4 v1 = *(const float4*)(h2 + (size_t)s1 * 128 + lane * 4);
        float4 v2 = *(const float4*)(h2 + (size_t)s2 * 128 + lane * 4);
        float4 v3 = *(const float4*)(h2 + (size_t)s3 * 128 + lane * 4);
        acc.x += v0.x*e0 + v1.x*e1 + v2.x*e2 + v3.x*e3;
        acc.y += v0.y*e0 + v1.y*e1 + v2.y*e2 + v3.y*e3;
        acc.z += v0.z*e0 + v1.z*e1 + v2.z*e2 + v3.z*e3;
        acc.w += v0.w*e0 + v1.w*e1 + v2.w*e2 + v3.w*e3;
    }
    for (; i < end; i++) {
        int s = srcs[i];
        float e = __expf(leaky(as_[s * 2 + hh] + adS) - cS);
        den += e;
        float4 v = *(const float4*)(h2 + (size_t)s * 128 + lane * 4);
        acc.x += v.x * e; acc.y += v.y * e; acc.z += v.z * e; acc.w += v.w * e;
    }
    float scale = __fdividef(1.f, den);
    acc.x *= scale; acc.y *= scale; acc.z *= scale; acc.w *= scale;

    float ox = __shfl_down_sync(0xffffffffu, acc.x, 16);
    float oy = __shfl_down_sync(0xffffffffu, acc.y, 16);
    float oz = __shfl_down_sync(0xffffffffu, acc.z, 16);
    float ow = __shfl_down_sync(0xffffffffu, acc.w, 16);
    if (h0) {
        float4 b = *(const float4*)&bg[lane * 4];
        float4 r;
        r.x = 0.5f * (acc.x + ox) + b.x;
        r.y = 0.5f * (acc.y + oy) + b.y;
        r.z = 0.5f * (acc.z + oz) + b.z;
        r.w = 0.5f * (acc.w + ow) + b.w;
        r.x = r.x > 0.f ? r.x : expm1f(r.x);
        r.y = r.y > 0.f ? r.y : expm1f(r.y);
        r.z = r.z > 0.f ? r.z : expm1f(r.z);
        r.w = r.w > 0.f ? r.w : expm1f(r.w);
        *(float4*)(hx + (size_t)d * 64 + lane * 4) = r;
    }
}

// ---------------- GCN2 pull-aggregation (F=64): pure gather-add (h pre-scaled) ------------
__global__ void k_gcn2_agg(const float* __restrict__ h, const int* __restrict__ off,
                           const int* __restrict__ deg, const int* __restrict__ srcs,
                           const float* __restrict__ inv, const float* __restrict__ bias,
                           float* __restrict__ out, int n)
{
    int gid = blockIdx.x * blockDim.x + threadIdx.x;
    int d = gid >> 5, lane = gid & 31;
    if (d >= n) return;
    int beg = off[d], end = beg + deg[d];
    float invd = inv[d];

    float2 acc = *(const float2*)(h + (size_t)d * 64 + lane * 2);

    int i = beg;
    for (; i + 4 <= end; i += 4) {
        int s0 = srcs[i], s1 = srcs[i+1], s2 = srcs[i+2], s3 = srcs[i+3];
        float2 v0 = *(const float2*)(h + (size_t)s0 * 64 + lane * 2);
        float2 v1 = *(const float2*)(h + (size_t)s1 * 64 + lane * 2);
        float2 v2 = *(const float2*)(h + (size_t)s2 * 64 + lane * 2);
        float2 v3 = *(const float2*)(h + (size_t)s3 * 64 + lane * 2);
        acc.x += (v0.x + v1.x) + (v2.x + v3.x);
        acc.y += (v0.y + v1.y) + (v2.y + v3.y);
    }
    for (; i < end; i++) {
        int s = srcs[i];
        float2 v = *(const float2*)(h + (size_t)s * 64 + lane * 2);
        acc.x += v.x; acc.y += v.y;
    }
    float2 b = *(const float2*)&bias[lane * 2];
    *(float2*)(out + (size_t)d * 64 + lane * 2) =
        make_float2(acc.x * invd + b.x, acc.y * invd + b.y);
}

// ---------------- host ----------------
static inline int up(int a, int b) { return (a + b - 1) / b; }

extern "C" void kernel_launch(void* const* d_in, const int* in_sizes, int n_in,
                              void* d_out, int out_size)
{
    const float* x       = (const float*)d_in[0];
    const int*   ei      = (const int*)d_in[1];    // int32 (JAX x64 disabled)
    const float* W1      = (const float*)d_in[2];
    const float* b1      = (const float*)d_in[3];
    const float* Wg      = (const float*)d_in[4];
    const float* att_src = (const float*)d_in[5];
    const float* att_dst = (const float*)d_in[6];
    const float* bg      = (const float*)d_in[7];
    const float* W3      = (const float*)d_in[8];
    const float* b3      = (const float*)d_in[9];
    float* out = (float*)d_out;

    int n = in_sizes[0] / 128;
    int E = in_sizes[1] / 2;
    const int* src = ei;
    const int* dst = ei + E;

    void* p;
    cudaGetSymbolAddress(&p, g_h1);    float* h1    = (float*)p;
    cudaGetSymbolAddress(&p, g_agg);   float* agg   = (float*)p;
    cudaGetSymbolAddress(&p, g_inv);   float* inv   = (float*)p;
    cudaGetSymbolAddress(&p, g_as);    float* as_   = (float*)p;
    cudaGetSymbolAddress(&p, g_ad);    float* ad_   = (float*)p;
    cudaGetSymbolAddress(&p, g_hx);    float* hx    = (float*)p;
    cudaGetSymbolAddress(&p, g_h3);    float* h3    = (float*)p;
    cudaGetSymbolAddress(&p, g_deg);   int*   deg   = (int*)p;
    cudaGetSymbolAddress(&p, g_off);   int*   off   = (int*)p;
    cudaGetSymbolAddress(&p, g_cur);   int*   cur   = (int*)p;
    cudaGetSymbolAddress(&p, g_srcs);  int*   srcs  = (int*)p;
    cudaGetSymbolAddress(&p, g_total); unsigned* total = (unsigned*)p;
    cudaGetSymbolAddress(&p, g_maxas); float* maxas = (float*)p;

    // fork-join side stream for CSR build (created once; capture-safe pattern)
    static cudaStream_t s2 = nullptr;
    static cudaEvent_t evFork = nullptr, evJoin = nullptr;
    if (!s2) {
        cudaStreamCreateWithFlags(&s2, cudaStreamNonBlocking);
        cudaEventCreateWithFlags(&evFork, cudaEventDisableTiming);
        cudaEventCreateWithFlags(&evJoin, cudaEventDisableTiming);
    }

    const int T = 256;

    // ---- fork: CSR build on s2, GEMM1 (unscaled) fully concurrent on default ----
    cudaEventRecord(evFork, 0);
    cudaStreamWaitEvent(s2, evFork, 0);

    k_zero_deg <<<up(n, T), T, 0, s2>>>(deg, total, maxas, n);
    k_deg_count<<<up(E, T * 4), T, 0, s2>>>(dst, deg, E);
    k_offsets  <<<up(n, T), T, 0, s2>>>(deg, off, cur, inv, total, n);
    k_fill     <<<up(E, T * 4), T, 0, s2>>>(src, dst, cur, srcs, E);
    cudaEventRecord(evJoin, s2);

    gemm_tf32<128,128,false><<<up(n, 128), 256>>>(x, W1, h1, inv, n);

    cudaStreamWaitEvent(0, evJoin, 0);   // CSR done before first aggregation

    // ---- GCN layer 1 (per-edge inv coefficients) ----
    k_gcn1_agg<<<up(n * 32, T), T>>>(h1, off, deg, srcs, inv, b1, agg, n);

    // ---- GAT layer ----
    gemm_tf32<128,128,false><<<up(n, 128), 256>>>(agg, Wg, h1, inv, n);   // h2 in h1
    k_gat_scores<<<up(n * 64, 1024), 1024>>>(h1, att_src, att_dst, as_, ad_, maxas, n);
    k_gat_agg   <<<up(n * 32, T), T>>>(h1, off, deg, srcs, as_, ad_, maxas, bg, hx, n);

    // ---- GCN layer 2 : h3 = (hx@W3)*inv fused (inv ready long ago) ----
    gemm_tf32<64,64,true><<<up(n, 128), 256>>>(hx, W3, h3, inv, n);
    k_gcn2_agg<<<up(n * 32, T), T>>>(h3, off, deg, srcs, inv, b3, out, n);
}

// round 16
// speedup vs baseline: 1.1031x; 1.0678x over previous
#include <cuda_runtime.h>
#include <cstdint>

// ---------------- scratch (device globals; no allocation) ----------------
#define NMAX 50000
#define EMAX 800000
__device__ float g_h1 [NMAX * 128];   // x@W1, later h2 (GAT transform)
__device__ float g_agg[NMAX * 128];   // relu(GCN1) output
__device__ float g_inv[NMAX];         // rsqrt(deg)
__device__ float g_as [NMAX * 2];     // GAT a_src per (node, head)
__device__ float g_ad [NMAX * 2];     // GAT a_dst per (node, head)
__device__ float g_hx [NMAX * 64];    // elu(mean-head GAT) = GCN2 input
__device__ float g_h3 [NMAX * 64];    // (hx @ W3)*inv
__device__ int   g_deg[NMAX];
__device__ int   g_off[NMAX];
__device__ int   g_cur[NMAX];
__device__ int   g_srcs[EMAX];        // src ids bucketed by dst
__device__ unsigned g_total;
__device__ float g_maxas[2];          // global per-head max of a_src

__device__ __forceinline__ float leaky(float v) { return v > 0.f ? v : 0.2f * v; }

__device__ __forceinline__ void atomicMaxF(float* a, float v) {
    if (v >= 0.f) atomicMax((int*)a, __float_as_int(v));
    else          atomicMin((unsigned int*)a, __float_as_uint(v));
}

// ---------------- degree + CSR build ----------------
__global__ void k_zero_deg(int* deg, unsigned* total, float* maxas, int n) {
    int i = blockIdx.x * blockDim.x + threadIdx.x;
    if (i < n) deg[i] = 0;
    if (i == 0) { *total = 0u; maxas[0] = -3e38f; maxas[1] = -3e38f; }
}
__global__ void k_deg_count(const int* __restrict__ dst, int* deg, int E) {
    int base = (blockIdx.x * blockDim.x + threadIdx.x) * 4;
    #pragma unroll
    for (int j = 0; j < 4; j++) {
        int i = base + j;
        if (i < E) atomicAdd(&deg[dst[i]], 1);
    }
}
__global__ void k_offsets(const int* __restrict__ deg, int* off, int* cur,
                          float* inv, unsigned* total, int n) {
    int i = blockIdx.x * blockDim.x + threadIdx.x;
    int lane = threadIdx.x & 31;
    int d = (i < n) ? deg[i] : 0;
    int x = d;
    #pragma unroll
    for (int o = 1; o < 32; o <<= 1) {
        int y = __shfl_up_sync(0xffffffffu, x, o);
        if (lane >= o) x += y;
    }
    int wsum = __shfl_sync(0xffffffffu, x, 31);
    unsigned base = 0;
    if (lane == 31) base = atomicAdd(total, (unsigned)wsum);
    base = __shfl_sync(0xffffffffu, base, 31);
    int excl = (int)base + x - d;
    if (i < n) {
        off[i] = excl; cur[i] = excl;
        inv[i] = rsqrtf((float)(d + 1));
    }
}
__global__ void k_fill(const int* __restrict__ src, const int* __restrict__ dst,
                       int* cur, int* srcs, int E) {
    int base = (blockIdx.x * blockDim.x + threadIdx.x) * 4;
    #pragma unroll
    for (int j = 0; j < 4; j++) {
        int i = base + j;
        if (i < E) {
            int pos = atomicAdd(&cur[dst[i]], 1);
            srcs[pos] = src[i];
        }
    }
}

// ---------------- TF32 tensor-core GEMM with error compensation ----------------
// SCALE:  multiply output rows by inv[row] (fused GCN degree pre-scaling)
// SCORES: also compute GAT a_src/a_dst per (row, head) from the output fragments
//         (warp column-group wn covers exactly head wn's 64 columns)
__device__ __forceinline__ void split_tf32(float x, uint32_t& hi, uint32_t& lo) {
    uint32_t h;
    asm("cvt.rna.tf32.f32 %0, %1;" : "=r"(h) : "f"(x));
    float l = x - __uint_as_float(h);
    uint32_t lw;
    asm("cvt.rna.tf32.f32 %0, %1;" : "=r"(lw) : "f"(l));
    hi = h; lo = lw;
}
__device__ __forceinline__ void mma_tf32(float* c, const uint32_t* a, const uint32_t* b) {
    asm volatile("mma.sync.aligned.m16n8k8.row.col.f32.tf32.tf32.f32 "
        "{%0,%1,%2,%3},{%4,%5,%6,%7},{%8,%9},{%0,%1,%2,%3};"
        : "+f"(c[0]), "+f"(c[1]), "+f"(c[2]), "+f"(c[3])
        : "r"(a[0]), "r"(a[1]), "r"(a[2]), "r"(a[3]), "r"(b[0]), "r"(b[1]));
}

template<int K, int P, bool SCALE, bool SCORES>
__global__ void __launch_bounds__(256)
gemm_tf32(const float* __restrict__ X, const float* __restrict__ W,
          float* __restrict__ Y, const float* __restrict__ inv,
          const float* __restrict__ att_s, const float* __restrict__ att_d,
          float* __restrict__ as_, float* __restrict__ ad_,
          float* __restrict__ maxas, int n)
{
    constexpr int BM = 128;
    constexpr int BK = 32;
    constexpr int WARPS_N = P / 64;
    constexpr int WARPS_M = 8 / WARPS_N;
    constexpr int WM = BM / WARPS_M;
    constexpr int MF = WM / 16;
    constexpr int NF = 8;
    constexpr int XS = BK + 4;
    constexpr int WS = P + 8;

    __shared__ __align__(16) float Xs[BM * XS];
    __shared__ __align__(16) float Ws[BK * WS];
    __shared__ float smax[2];

    int tid = threadIdx.x;
    int wid = tid >> 5, lane = tid & 31;
    int wm = wid % WARPS_M, wn = wid / WARPS_M;
    int g = lane >> 2, tg = lane & 3;

    if (SCORES && tid < 2) smax[tid] = -3e38f;

    int r0 = blockIdx.x * BM;
    int rows = n - r0; if (rows > BM) rows = BM;

    float c[MF][NF][4];
    #pragma unroll
    for (int mf = 0; mf < MF; mf++)
        #pragma unroll
        for (int nf = 0; nf < NF; nf++)
            #pragma unroll
            for (int q = 0; q < 4; q++) c[mf][nf][q] = 0.f;

    for (int kt = 0; kt < K; kt += BK) {
        #pragma unroll
        for (int i = tid; i < BK * P / 4; i += 256) {
            int k = i / (P / 4), c4 = (i % (P / 4)) * 4;
            *(float4*)&Ws[k * WS + c4] = *(const float4*)&W[(kt + k) * P + c4];
        }
        #pragma unroll
        for (int i = tid; i < BM * BK / 4; i += 256) {
            int r = i / (BK / 4), k4 = (i % (BK / 4)) * 4;
            float4 v = (r < rows) ? *(const float4*)&X[(size_t)(r0 + r) * K + kt + k4]
                                  : make_float4(0.f, 0.f, 0.f, 0.f);
            *(float4*)&Xs[r * XS + k4] = v;
        }
        __syncthreads();
        #pragma unroll
        for (int k8 = 0; k8 < BK; k8 += 8) {
            uint32_t ah[MF][4], al[MF][4];
            #pragma unroll
            for (int mf = 0; mf < MF; mf++) {
                int rb = wm * WM + mf * 16;
                split_tf32(Xs[(rb + g    ) * XS + k8 + tg    ], ah[mf][0], al[mf][0]);
                split_tf32(Xs[(rb + g + 8) * XS + k8 + tg    ], ah[mf][1], al[mf][1]);
                split_tf32(Xs[(rb + g    ) * XS + k8 + tg + 4], ah[mf][2], al[mf][2]);
                split_tf32(Xs[(rb + g + 8) * XS + k8 + tg + 4], ah[mf][3], al[mf][3]);
            }
            uint32_t bh[NF][2], bl[NF][2];
            #pragma unroll
            for (int nf = 0; nf < NF; nf++) {
                int col = wn * 64 + nf * 8 + g;
                split_tf32(Ws[(k8 + tg    ) * WS + col], bh[nf][0], bl[nf][0]);
                split_tf32(Ws[(k8 + tg + 4) * WS + col], bh[nf][1], bl[nf][1]);
            }
            #pragma unroll
            for (int mf = 0; mf < MF; mf++)
                #pragma unroll
                for (int nf = 0; nf < NF; nf++) {
                    mma_tf32(c[mf][nf], ah[mf], bh[nf]);
                    mma_tf32(c[mf][nf], ah[mf], bl[nf]);
                    mma_tf32(c[mf][nf], al[mf], bh[nf]);
                }
        }
        __syncthreads();
    }
    #pragma unroll
    for (int mf = 0; mf < MF; mf++) {
        int rb = wm * WM + mf * 16;
        int ra = rb + g, rc = rb + g + 8;
        float iva = 1.f, ivc = 1.f;
        if (SCALE) {
            if (ra < rows) iva = inv[r0 + ra];
            if (rc < rows) ivc = inv[r0 + rc];
        }
        #pragma unroll
        for (int nf = 0; nf < NF; nf++) {
            int col = wn * 64 + nf * 8 + 2 * tg;
            if (ra < rows)
                *(float2*)&Y[(size_t)(r0 + ra) * P + col] =
                    make_float2(c[mf][nf][0] * iva, c[mf][nf][1] * iva);
            if (rc < rows)
                *(float2*)&Y[(size_t)(r0 + rc) * P + col] =
                    make_float2(c[mf][nf][2] * ivc, c[mf][nf][3] * ivc);
        }
    }
    if (SCORES) {
        // this thread's 16 cols of head wn: j = nf*8 + 2tg (+1)
        float asv[NF * 2], adv[NF * 2];
        #pragma unroll
        for (int nf = 0; nf < NF; nf++) {
            int j = nf * 8 + 2 * tg;
            asv[nf*2]   = att_s[wn * 64 + j];
            asv[nf*2+1] = att_s[wn * 64 + j + 1];
            adv[nf*2]   = att_d[wn * 64 + j];
            adv[nf*2+1] = att_d[wn * 64 + j + 1];
        }
        #pragma unroll
        for (int mf = 0; mf < MF; mf++) {
            float sa = 0.f, da = 0.f, sc = 0.f, dc = 0.f;
            #pragma unroll
            for (int nf = 0; nf < NF; nf++) {
                sa += c[mf][nf][0]*asv[nf*2] + c[mf][nf][1]*asv[nf*2+1];
                da += c[mf][nf][0]*adv[nf*2] + c[mf][nf][1]*adv[nf*2+1];
                sc += c[mf][nf][2]*asv[nf*2] + c[mf][nf][3]*asv[nf*2+1];
                dc += c[mf][nf][2]*adv[nf*2] + c[mf][nf][3]*adv[nf*2+1];
            }
            // quad reduce across tg (lanes 4g+tg)
            #pragma unroll
            for (int o = 1; o < 4; o <<= 1) {
                sa += __shfl_xor_sync(0xffffffffu, sa, o);
                da += __shfl_xor_sync(0xffffffffu, da, o);
                sc += __shfl_xor_sync(0xffffffffu, sc, o);
                dc += __shfl_xor_sync(0xffffffffu, dc, o);
            }
            int rb = wm * WM + mf * 16;
            int ra = rb + g, rc = rb + g + 8;
            if (tg == 0) {
                if (ra < rows) {
                    as_[(size_t)(r0 + ra) * 2 + wn] = sa;
                    ad_[(size_t)(r0 + ra) * 2 + wn] = da;
                    if (sa >= 0.f) atomicMax((int*)&smax[wn], __float_as_int(sa));
                    else           atomicMin((unsigned int*)&smax[wn], __float_as_uint(sa));
                }
                if (rc < rows) {
                    as_[(size_t)(r0 + rc) * 2 + wn] = sc;
                    ad_[(size_t)(r0 + rc) * 2 + wn] = dc;
                    if (sc >= 0.f) atomicMax((int*)&smax[wn], __float_as_int(sc));
                    else           atomicMin((unsigned int*)&smax[wn], __float_as_uint(sc));
                }
            }
        }
        __syncthreads();
        if (tid < 2) atomicMaxF(&maxas[tid], smax[tid]);
    }
}

// ---------------- GCN1 pull-aggregation (F=128) + relu, warp/node, unroll-4 ----------------
__global__ void k_gcn1_agg(const float* __restrict__ h, const int* __restrict__ off,
                           const int* __restrict__ deg, const int* __restrict__ srcs,
                           const float* __restrict__ inv, const float* __restrict__ bias,
                           float* __restrict__ out, int n)
{
    int gid = blockIdx.x * blockDim.x + threadIdx.x;
    int d = gid >> 5, lane = gid & 31;
    if (d >= n) return;
    int beg = off[d], end = beg + deg[d];
    float invd = inv[d];

    float4 sv = *(const float4*)(h + (size_t)d * 128 + lane * 4);
    float cs = invd * invd;
    float4 acc = make_float4(sv.x * cs, sv.y * cs, sv.z * cs, sv.w * cs);

    int i = beg;
    for (; i + 4 <= end; i += 4) {
        int s0 = srcs[i], s1 = srcs[i+1], s2 = srcs[i+2], s3 = srcs[i+3];
        float c0 = inv[s0] * invd, c1 = inv[s1] * invd;
        float c2 = inv[s2] * invd, c3 = inv[s3] * invd;
        float4 v0 = *(const float4*)(h + (size_t)s0 * 128 + lane * 4);
        float4 v1 = *(const float4*)(h + (size_t)s1 * 128 + lane * 4);
        float4 v2 = *(const float4*)(h + (size_t)s2 * 128 + lane * 4);
        float4 v3 = *(const float4*)(h + (size_t)s3 * 128 + lane * 4);
        acc.x += v0.x*c0 + v1.x*c1 + v2.x*c2 + v3.x*c3;
        acc.y += v0.y*c0 + v1.y*c1 + v2.y*c2 + v3.y*c3;
        acc.z += v0.z*c0 + v1.z*c1 + v2.z*c2 + v3.z*c3;
        acc.w += v0.w*c0 + v1.w*c1 + v2.w*c2 + v3.w*c3;
    }
    for (; i < end; i++) {
        int s = srcs[i];
        float c = inv[s] * invd;
        float4 v = *(const float4*)(h + (size_t)s * 128 + lane * 4);
        acc.x += v.x * c; acc.y += v.y * c; acc.z += v.z * c; acc.w += v.w * c;
    }
    float4 b = *(const float4*)&bias[lane * 4];
    acc.x = fmaxf(acc.x + b.x, 0.f); acc.y = fmaxf(acc.y + b.y, 0.f);
    acc.z = fmaxf(acc.z + b.z, 0.f); acc.w = fmaxf(acc.w + b.w, 0.f);
    *(float4*)(out + (size_t)d * 128 + lane * 4) = acc;
}

// ---------------- GAT single-pass softmax+aggregation, 1 exp/edge/lane -------------------
__global__ void k_gat_agg(const float* __restrict__ h2, const int* __restrict__ off,
                          const int* __restrict__ deg, const int* __restrict__ srcs,
                          const float* __restrict__ as_, const float* __restrict__ ad_,
                          const float* __restrict__ maxas, const float* __restrict__ bg,
                          float* __restrict__ hx, int n)
{
    int gid = blockIdx.x * blockDim.x + threadIdx.x;
    int d = gid >> 5, lane = gid & 31;
    if (d >= n) return;
    int beg = off[d], end = beg + deg[d];
    bool h0 = lane < 16;
    int hh = h0 ? 0 : 1;

    float adS = ad_[d * 2 + hh];
    float cS  = leaky(maxas[hh] + adS);
    float exs = __expf(leaky(as_[d * 2 + hh] + adS) - cS);
    float den = exs;

    float4 sv = *(const float4*)(h2 + (size_t)d * 128 + lane * 4);
    float4 acc = make_float4(sv.x * exs, sv.y * exs, sv.z * exs, sv.w * exs);

    int i = beg;
    for (; i + 4 <= end; i += 4) {
        int s0 = srcs[i], s1 = srcs[i+1], s2 = srcs[i+2], s3 = srcs[i+3];
        float e0 = __expf(leaky(as_[s0 * 2 + hh] + adS) - cS);
        float e1 = __expf(leaky(as_[s1 * 2 + hh] + adS) - cS);
        float e2 = __expf(leaky(as_[s2 * 2 + hh] + adS) - cS);
        float e3 = __expf(leaky(as_[s3 * 2 + hh] + adS) - cS);
        den += (e0 + e1) + (e2 + e3);
        float4 v0 = *(const float4*)(h2 + (size_t)s0 * 128 + lane * 4);
        float4 v1 = *(const float4*)(h2 + (size_t)s1 * 128 + lane * 4);
        float4 v2 = *(const float4*)(h2 + (size_t)s2 * 128 + lane * 4);
        float4 v3 = *(const float4*)(h2 + (size_t)s3 * 128 + lane * 4);
        acc.x += v0.x*e0 + v1.x*e1 + v2.x*e2 + v3.x*e3;
        acc.y += v0.y*e0 + v1.y*e1 + v2.y*e2 + v3.y*e3;
        acc.z += v0.z*e0 + v1.z*e1 + v2.z*e2 + v3.z*e3;
        acc.w += v0.w*e0 + v1.w*e1 + v2.w*e2 + v3.w*e3;
    }
    for (; i < end; i++) {
        int s = srcs[i];
        float e = __expf(leaky(as_[s * 2 + hh] + adS) - cS);
        den += e;
        float4 v = *(const float4*)(h2 + (size_t)s * 128 + lane * 4);
        acc.x += v.x * e; acc.y += v.y * e; acc.z += v.z * e; acc.w += v.w * e;
    }
    float scale = __fdividef(1.f, den);
    acc.x *= scale; acc.y *= scale; acc.z *= scale; acc.w *= scale;

    float ox = __shfl_down_sync(0xffffffffu, acc.x, 16);
    float oy = __shfl_down_sync(0xffffffffu, acc.y, 16);
    float oz = __shfl_down_sync(0xffffffffu, acc.z, 16);
    float ow = __shfl_down_sync(0xffffffffu, acc.w, 16);
    if (h0) {
        float4 b = *(const float4*)&bg[lane * 4];
        float4 r;
        r.x = 0.5f * (acc.x + ox) + b.x;
        r.y = 0.5f * (acc.y + oy) + b.y;
        r.z = 0.5f * (acc.z + oz) + b.z;
        r.w = 0.5f * (acc.w + ow) + b.w;
        r.x = r.x > 0.f ? r.x : expm1f(r.x);
        r.y = r.y > 0.f ? r.y : expm1f(r.y);
        r.z = r.z > 0.f ? r.z : expm1f(r.z);
        r.w = r.w > 0.f ? r.w : expm1f(r.w);
        *(float4*)(hx + (size_t)d * 64 + lane * 4) = r;
    }
}

// ---------------- GCN2 pull-aggregation (F=64): pure gather-add (h pre-scaled) ------------
__global__ void k_gcn2_agg(const float* __restrict__ h, const int* __restrict__ off,
                           const int* __restrict__ deg, const int* __restrict__ srcs,
                           const float* __restrict__ inv, const float* __restrict__ bias,
                           float* __restrict__ out, int n)
{
    int gid = blockIdx.x * blockDim.x + threadIdx.x;
    int d = gid >> 5, lane = gid & 31;
    if (d >= n) return;
    int beg = off[d], end = beg + deg[d];
    float invd = inv[d];

    float2 acc = *(const float2*)(h + (size_t)d * 64 + lane * 2);

    int i = beg;
    for (; i + 4 <= end; i += 4) {
        int s0 = srcs[i], s1 = srcs[i+1], s2 = srcs[i+2], s3 = srcs[i+3];
        float2 v0 = *(const float2*)(h + (size_t)s0 * 64 + lane * 2);
        float2 v1 = *(const float2*)(h + (size_t)s1 * 64 + lane * 2);
        float2 v2 = *(const float2*)(h + (size_t)s2 * 64 + lane * 2);
        float2 v3 = *(const float2*)(h + (size_t)s3 * 64 + lane * 2);
        acc.x += (v0.x + v1.x) + (v2.x + v3.x);
        acc.y += (v0.y + v1.y) + (v2.y + v3.y);
    }
    for (; i < end; i++) {
        int s = srcs[i];
        float2 v = *(const float2*)(h + (size_t)s * 64 + lane * 2);
        acc.x += v.x; acc.y += v.y;
    }
    float2 b = *(const float2*)&bias[lane * 2];
    *(float2*)(out + (size_t)d * 64 + lane * 2) =
        make_float2(acc.x * invd + b.x, acc.y * invd + b.y);
}

// ---------------- host ----------------
static inline int up(int a, int b) { return (a + b - 1) / b; }

extern "C" void kernel_launch(void* const* d_in, const int* in_sizes, int n_in,
                              void* d_out, int out_size)
{
    const float* x       = (const float*)d_in[0];
    const int*   ei      = (const int*)d_in[1];    // int32 (JAX x64 disabled)
    const float* W1      = (const float*)d_in[2];
    const float* b1      = (const float*)d_in[3];
    const float* Wg      = (const float*)d_in[4];
    const float* att_src = (const float*)d_in[5];
    const float* att_dst = (const float*)d_in[6];
    const float* bg      = (const float*)d_in[7];
    const float* W3      = (const float*)d_in[8];
    const float* b3      = (const float*)d_in[9];
    float* out = (float*)d_out;

    int n = in_sizes[0] / 128;
    int E = in_sizes[1] / 2;
    const int* src = ei;
    const int* dst = ei + E;

    void* p;
    cudaGetSymbolAddress(&p, g_h1);    float* h1    = (float*)p;
    cudaGetSymbolAddress(&p, g_agg);   float* agg   = (float*)p;
    cudaGetSymbolAddress(&p, g_inv);   float* inv   = (float*)p;
    cudaGetSymbolAddress(&p, g_as);    float* as_   = (float*)p;
    cudaGetSymbolAddress(&p, g_ad);    float* ad_   = (float*)p;
    cudaGetSymbolAddress(&p, g_hx);    float* hx    = (float*)p;
    cudaGetSymbolAddress(&p, g_h3);    float* h3    = (float*)p;
    cudaGetSymbolAddress(&p, g_deg);   int*   deg   = (int*)p;
    cudaGetSymbolAddress(&p, g_off);   int*   off   = (int*)p;
    cudaGetSymbolAddress(&p, g_cur);   int*   cur   = (int*)p;
    cudaGetSymbolAddress(&p, g_srcs);  int*   srcs  = (int*)p;
    cudaGetSymbolAddress(&p, g_total); unsigned* total = (unsigned*)p;
    cudaGetSymbolAddress(&p, g_maxas); float* maxas = (float*)p;

    // fork-join side stream for CSR build (created once; capture-safe pattern)
    static cudaStream_t s2 = nullptr;
    static cudaEvent_t evFork = nullptr, evJoin = nullptr;
    if (!s2) {
        cudaStreamCreateWithFlags(&s2, cudaStreamNonBlocking);
        cudaEventCreateWithFlags(&evFork, cudaEventDisableTiming);
        cudaEventCreateWithFlags(&evJoin, cudaEventDisableTiming);
    }

    const int T = 256;

    // ---- fork: CSR build on s2, GEMM1 fully concurrent on default ----
    cudaEventRecord(evFork, 0);
    cudaStreamWaitEvent(s2, evFork, 0);

    k_zero_deg <<<up(n, T), T, 0, s2>>>(deg, total, maxas, n);
    k_deg_count<<<up(E, T * 4), T, 0, s2>>>(dst, deg, E);
    k_offsets  <<<up(n, T), T, 0, s2>>>(deg, off, cur, inv, total, n);
    k_fill     <<<up(E, T * 4), T, 0, s2>>>(src, dst, cur, srcs, E);
    cudaEventRecord(evJoin, s2);

    gemm_tf32<128,128,false,false><<<up(n, 128), 256>>>(
        x, W1, h1, inv, nullptr, nullptr, nullptr, nullptr, nullptr, n);

    cudaStreamWaitEvent(0, evJoin, 0);   // CSR done before first aggregation

    // ---- GCN layer 1 (per-edge inv coefficients) ----
    k_gcn1_agg<<<up(n * 32, T), T>>>(h1, off, deg, srcs, inv, b1, agg, n);

    // ---- GAT layer : GEMM2 epilogue computes a_src/a_dst/maxas ----
    gemm_tf32<128,128,false,true><<<up(n, 128), 256>>>(
        agg, Wg, h1, inv, att_src, att_dst, as_, ad_, maxas, n);
    k_gat_agg<<<up(n * 32, T), T>>>(h1, off, deg, srcs, as_, ad_, maxas, bg, hx, n);

    // ---- GCN layer 2 : h3 = (hx@W3)*inv fused ----
    gemm_tf32<64,64,true,false><<<up(n, 128), 256>>>(
        hx, W3, h3, inv, nullptr, nullptr, nullptr, nullptr, nullptr, n);
    k_gcn2_agg<<<up(n * 32, T), T>>>(h3, off, deg, srcs, inv, b3, out, n);
}